// round 5
// baseline (speedup 1.0000x reference)
#include <cuda_runtime.h>
#include <cstdint>
#include <cstddef>

#define BATCH 8192
#define UNITS 1024
#define AR 12
#define RR 64
#define NP 30
#define ENC 76          // 12 + 64
#define G3 3072         // 3*UNITS
#define LDY 3200        // padded N for the fused GEMM (3072 gh + 12 ang + 64 rad + pad)

// output layout: a_oh | a_prob | r_oh | r_prob, each [B, NP, dim]
#define OFF_APROB (BATCH*NP*AR)
#define OFF_ROH   (2*BATCH*NP*AR)
#define OFF_RPROB (2*BATCH*NP*AR + BATCH*NP*RR)

// ------------------------- scratch (static device globals) -------------------------
__device__ float g_h[(size_t)BATCH * UNITS];
__device__ float g_Y[(size_t)BATCH * LDY];
__device__ float g_Wcat[(size_t)UNITS * LDY];
__device__ float g_C[(size_t)ENC * G3];
__device__ float g_cb[G3];
__device__ int   g_aidx[BATCH];
__device__ int   g_ridx[BATCH];

// ------------------------- threefry2x32 (exact JAX) -------------------------
__host__ __device__ __forceinline__ uint32_t rotl32(uint32_t x, int d) {
    return (x << d) | (x >> (32 - d));
}

__host__ __device__ __forceinline__ void threefry2x32(
    uint32_t k0, uint32_t k1, uint32_t c0, uint32_t c1,
    uint32_t& o0, uint32_t& o1)
{
    uint32_t ks2 = k0 ^ k1 ^ 0x1BD11BDAu;
    uint32_t x0 = c0 + k0;
    uint32_t x1 = c1 + k1;
    // rounds 1-4 (13,15,26,6)
    x0 += x1; x1 = rotl32(x1, 13); x1 ^= x0;
    x0 += x1; x1 = rotl32(x1, 15); x1 ^= x0;
    x0 += x1; x1 = rotl32(x1, 26); x1 ^= x0;
    x0 += x1; x1 = rotl32(x1, 6);  x1 ^= x0;
    x0 += k1; x1 += ks2 + 1u;
    // rounds 5-8 (17,29,16,24)
    x0 += x1; x1 = rotl32(x1, 17); x1 ^= x0;
    x0 += x1; x1 = rotl32(x1, 29); x1 ^= x0;
    x0 += x1; x1 = rotl32(x1, 16); x1 ^= x0;
    x0 += x1; x1 = rotl32(x1, 24); x1 ^= x0;
    x0 += ks2; x1 += k0 + 2u;
    // rounds 9-12
    x0 += x1; x1 = rotl32(x1, 13); x1 ^= x0;
    x0 += x1; x1 = rotl32(x1, 15); x1 ^= x0;
    x0 += x1; x1 = rotl32(x1, 26); x1 ^= x0;
    x0 += x1; x1 = rotl32(x1, 6);  x1 ^= x0;
    x0 += k0; x1 += k1 + 3u;
    // rounds 13-16
    x0 += x1; x1 = rotl32(x1, 17); x1 ^= x0;
    x0 += x1; x1 = rotl32(x1, 29); x1 ^= x0;
    x0 += x1; x1 = rotl32(x1, 16); x1 ^= x0;
    x0 += x1; x1 = rotl32(x1, 24); x1 ^= x0;
    x0 += k1; x1 += ks2 + 4u;
    // rounds 17-20
    x0 += x1; x1 = rotl32(x1, 13); x1 ^= x0;
    x0 += x1; x1 = rotl32(x1, 15); x1 ^= x0;
    x0 += x1; x1 = rotl32(x1, 26); x1 ^= x0;
    x0 += x1; x1 = rotl32(x1, 6);  x1 ^= x0;
    x0 += ks2; x1 += k0 + 5u;
    o0 = x0; o1 = x1;
}

// partitionable random_bits (JAX >= 0.5 default): element i of a 32-bit draw is
// xor-fold of the two threefry outputs on counter (i>>32, i&0xffffffff) == (0, i)
__device__ __forceinline__ float jax_gumbel_part(uint32_t k0, uint32_t k1, uint32_t i) {
    uint32_t o0, o1;
    threefry2x32(k0, k1, 0u, i, o0, o1);
    uint32_t bits = o0 ^ o1;
    float u = __uint_as_float((bits >> 9) | 0x3f800000u) - 1.0f;
    u = fmaxf(u, 1.17549435e-38f);
    return -logf(-logf(u));
}

// ------------------------- setup kernels -------------------------
__global__ void build_Wcat(const float* __restrict__ U,
                           const float* __restrict__ Wang,
                           const float* __restrict__ Wrad)
{
    int idx = blockIdx.x * 256 + threadIdx.x;
    if (idx >= UNITS * LDY) return;
    int k = idx / LDY, n = idx % LDY;
    float v;
    if (n < G3)            v = U[(size_t)k * G3 + n];
    else if (n < G3 + AR)  v = Wang[k * AR + (n - G3)];
    else if (n < G3 + ENC) v = Wrad[k * RR + (n - G3 - AR)];
    else                   v = 0.0f;
    g_Wcat[idx] = v;
}

__global__ void build_C(const float* __restrict__ W_enc, const float* __restrict__ b_enc,
                        const float* __restrict__ W_gru, const float* __restrict__ b_gru)
{
    __shared__ float sw[16][80];
    int j = blockIdx.x * 128 + threadIdx.x;
    float acc[77];
    #pragma unroll
    for (int p = 0; p < 77; p++) acc[p] = 0.0f;
    for (int k0 = 0; k0 < UNITS; k0 += 16) {
        __syncthreads();
        for (int idx = threadIdx.x; idx < 16 * 77; idx += 128) {
            int kk = idx / 77, p = idx % 77;
            sw[kk][p] = (p < ENC) ? W_enc[p * UNITS + k0 + kk] : b_enc[k0 + kk];
        }
        __syncthreads();
        #pragma unroll 4
        for (int kk = 0; kk < 16; kk++) {
            float wg = W_gru[(size_t)(k0 + kk) * G3 + j];
            #pragma unroll
            for (int p = 0; p < 77; p++) acc[p] = fmaf(sw[kk][p], wg, acc[p]);
        }
    }
    for (int p = 0; p < ENC; p++) g_C[(size_t)p * G3 + j] = acc[p];
    g_cb[j] = acc[76] + b_gru[j];
}

__global__ void copy_h(const float* __restrict__ s)
{
    int idx = blockIdx.x * 256 + threadIdx.x;
    if (idx < BATCH * UNITS) g_h[idx] = s[idx];
}

// ------------------------- fused GEMM: Y = h @ Wcat -------------------------
__global__ void __launch_bounds__(256) sgemm_nt(int ntile0)
{
    __shared__ __align__(16) float As[2][8][128];
    __shared__ __align__(16) float Bs[2][8][128];
    const int K = UNITS;
    const int m0 = blockIdx.x * 128;
    const int n0 = (blockIdx.y + ntile0) * 128;
    const int tid = threadIdx.x;
    const int arow = tid >> 1, acol = (tid & 1) << 2;
    const int brow = tid >> 5, bcol = (tid & 31) << 2;
    const float* Ap = g_h   + (size_t)(m0 + arow) * K + acol;
    const float* Bp = g_Wcat + (size_t)brow * LDY + n0 + bcol;

    float4 av = *(const float4*)Ap;
    float4 bv = *(const float4*)Bp;
    As[0][acol + 0][arow] = av.x;
    As[0][acol + 1][arow] = av.y;
    As[0][acol + 2][arow] = av.z;
    As[0][acol + 3][arow] = av.w;
    *(float4*)&Bs[0][brow][bcol] = bv;
    __syncthreads();

    const int ty = tid >> 4, tx = tid & 15;
    float acc[8][8];
    #pragma unroll
    for (int i = 0; i < 8; i++)
        #pragma unroll
        for (int j = 0; j < 8; j++) acc[i][j] = 0.0f;

    int buf = 0;
    for (int k0 = 8; k0 < K + 8; k0 += 8) {
        float4 av2, bv2;
        const bool more = (k0 < K);
        if (more) {
            av2 = *(const float4*)(Ap + k0);
            bv2 = *(const float4*)(Bp + (size_t)k0 * LDY);
        }
        #pragma unroll
        for (int kk = 0; kk < 8; kk++) {
            float4 a0 = *(const float4*)&As[buf][kk][ty * 8];
            float4 a1 = *(const float4*)&As[buf][kk][ty * 8 + 4];
            float4 b0 = *(const float4*)&Bs[buf][kk][tx * 8];
            float4 b1 = *(const float4*)&Bs[buf][kk][tx * 8 + 4];
            float ar[8] = {a0.x, a0.y, a0.z, a0.w, a1.x, a1.y, a1.z, a1.w};
            float br[8] = {b0.x, b0.y, b0.z, b0.w, b1.x, b1.y, b1.z, b1.w};
            #pragma unroll
            for (int i = 0; i < 8; i++)
                #pragma unroll
                for (int j = 0; j < 8; j++)
                    acc[i][j] = fmaf(ar[i], br[j], acc[i][j]);
        }
        if (more) {
            buf ^= 1;
            As[buf][acol + 0][arow] = av2.x;
            As[buf][acol + 1][arow] = av2.y;
            As[buf][acol + 2][arow] = av2.z;
            As[buf][acol + 3][arow] = av2.w;
            *(float4*)&Bs[buf][brow][bcol] = bv2;
            __syncthreads();
        }
    }
    #pragma unroll
    for (int i = 0; i < 8; i++) {
        float* Crow = g_Y + (size_t)(m0 + ty * 8 + i) * LDY + n0 + tx * 8;
        float4 v0 = make_float4(acc[i][0], acc[i][1], acc[i][2], acc[i][3]);
        float4 v1 = make_float4(acc[i][4], acc[i][5], acc[i][6], acc[i][7]);
        *(float4*)Crow = v0;
        *(float4*)(Crow + 4) = v1;
    }
}

// ------------------------- GRU elementwise update -------------------------
__global__ void gru_update(const float* __restrict__ b_gru, int t)
{
    int idx = blockIdx.x * 256 + threadIdx.x;
    if (idx >= BATCH * UNITS) return;
    int b = idx >> 10, u = idx & 1023;
    float gxz, gxr, gxn;
    if (t == 0) {
        gxz = b_gru[u]; gxr = b_gru[1024 + u]; gxn = b_gru[2048 + u];
    } else {
        int a = g_aidx[b], r = 12 + g_ridx[b];
        const float* Ca = g_C + (size_t)a * G3;
        const float* Cr = g_C + (size_t)r * G3;
        gxz = Ca[u]        + Cr[u]        + g_cb[u];
        gxr = Ca[1024 + u] + Cr[1024 + u] + g_cb[1024 + u];
        gxn = Ca[2048 + u] + Cr[2048 + u] + g_cb[2048 + u];
    }
    const float* Yb = g_Y + (size_t)b * LDY;
    float z = 1.0f / (1.0f + expf(-(gxz + Yb[u])));
    float r = 1.0f / (1.0f + expf(-(gxr + Yb[1024 + u])));
    float n = tanhf(gxn + r * Yb[2048 + u]);
    float hv = g_h[idx];
    g_h[idx] = z * hv + (1.0f - z) * n;
}

// ------------------------- sampling + outputs -------------------------
__global__ void sample_kernel(const float* __restrict__ b_ang, const float* __restrict__ b_rad,
                              float* __restrict__ out, int t,
                              uint32_t ka0, uint32_t ka1, uint32_t kr0, uint32_t kr1)
{
    const int b = blockIdx.x;
    const int j = threadIdx.x;     // 64 threads
    __shared__ float s1[64], s2[64];
    __shared__ float sh_max, sh_sum;
    __shared__ int sh_arg;
    const float* __restrict__ Yb = g_Y + (size_t)b * LDY;

    // -------- radius (64 classes) --------
    float rl = Yb[G3 + AR + j] + b_rad[j];
    {
        float g = jax_gumbel_part(kr0, kr1, (uint32_t)b * RR + j);
        s1[j] = rl;
        s2[j] = rl + g;
    }
    __syncthreads();
    if (j == 0) {
        float m = s1[0], bg = s2[0];
        int bi = 0;
        for (int q = 1; q < RR; q++) {
            m = fmaxf(m, s1[q]);
            if (s2[q] > bg) { bg = s2[q]; bi = q; }
        }
        sh_max = m; sh_arg = bi; g_ridx[b] = bi;
    }
    __syncthreads();
    float re = expf(rl - sh_max);
    s1[j] = re;
    __syncthreads();
    if (j == 0) {
        float s = 0.0f;
        for (int q = 0; q < RR; q++) s += s1[q];
        sh_sum = s;
    }
    __syncthreads();
    {
        size_t ro = ((size_t)b * NP + t) * RR + j;
        out[OFF_ROH + ro]   = (j == sh_arg) ? 1.0f : 0.0f;
        out[OFF_RPROB + ro] = re / sh_sum;
    }
    __syncthreads();

    // -------- angle (12 classes) --------
    float al = 0.0f;
    if (j < AR) {
        al = Yb[G3 + j] + b_ang[j];
        float g = jax_gumbel_part(ka0, ka1, (uint32_t)b * AR + j);
        s1[j] = al;
        s2[j] = al + g;
    }
    __syncthreads();
    if (j == 0) {
        float m = s1[0], bg = s2[0];
        int bi = 0;
        for (int q = 1; q < AR; q++) {
            m = fmaxf(m, s1[q]);
            if (s2[q] > bg) { bg = s2[q]; bi = q; }
        }
        sh_max = m; sh_arg = bi; g_aidx[b] = bi;
    }
    __syncthreads();
    float ae = 0.0f;
    if (j < AR) { ae = expf(al - sh_max); s1[j] = ae; }
    __syncthreads();
    if (j == 0) {
        float s = 0.0f;
        for (int q = 0; q < AR; q++) s += s1[q];
        sh_sum = s;
    }
    __syncthreads();
    if (j < AR) {
        size_t ao = ((size_t)b * NP + t) * AR + j;
        out[ao]             = (j == sh_arg) ? 1.0f : 0.0f;
        out[OFF_APROB + ao] = ae / sh_sum;
    }
}

// ------------------------- launch -------------------------
extern "C" void kernel_launch(void* const* d_in, const int* in_sizes, int n_in,
                              void* d_out, int out_size)
{
    (void)in_sizes; (void)n_in; (void)out_size;
    const float* s     = (const float*)d_in[0];
    const float* W_enc = (const float*)d_in[1];
    const float* b_enc = (const float*)d_in[2];
    const float* W_gru = (const float*)d_in[3];
    const float* U_gru = (const float*)d_in[4];
    const float* b_gru = (const float*)d_in[5];
    const float* W_ang = (const float*)d_in[6];
    const float* b_ang = (const float*)d_in[7];
    const float* W_rad = (const float*)d_in[8];
    const float* b_rad = (const float*)d_in[9];
    float* out = (float*)d_out;

    // ---- host-side JAX key schedule (partitionable threefry, JAX >= 0.5) ----
    // root = key(42) -> data (0, 42)
    // keys = split(root, 30): key_t = TF(root; 0, t)  (full 64-bit output)
    // k_a, k_r = split(key_t): k_a = TF(key_t; 0, 0), k_r = TF(key_t; 0, 1)
    uint32_t ka0[NP], ka1[NP], kr0[NP], kr1[NP];
    for (int t = 0; t < NP; t++) {
        uint32_t kt0, kt1;
        threefry2x32(0u, 42u, 0u, (uint32_t)t, kt0, kt1);
        threefry2x32(kt0, kt1, 0u, 0u, ka0[t], ka1[t]);
        threefry2x32(kt0, kt1, 0u, 1u, kr0[t], kr1[t]);
    }

    build_Wcat<<<(UNITS * LDY + 255) / 256, 256>>>(U_gru, W_ang, W_rad);
    build_C<<<24, 128>>>(W_enc, b_enc, W_gru, b_gru);
    copy_h<<<(BATCH * UNITS + 255) / 256, 256>>>(s);

    // pre-loop GEMM: gh_1 = s @ U_gru (tiles 0..23, logits of s unused)
    sgemm_nt<<<dim3(64, 24), 256>>>(0);

    for (int t = 0; t < NP; t++) {
        gru_update<<<(BATCH * UNITS + 255) / 256, 256>>>(b_gru, t);
        if (t < NP - 1) sgemm_nt<<<dim3(64, 25), 256>>>(0);   // logits(h_t) + gh(t+1)
        else            sgemm_nt<<<dim3(64, 1), 256>>>(24);   // last step: logits only
        sample_kernel<<<BATCH, 64>>>(b_ang, b_rad, out, t,
                                     ka0[t], ka1[t], kr0[t], kr1[t]);
    }
}

// round 6
// speedup vs baseline: 1.0811x; 1.0811x over previous
#include <cuda_runtime.h>
#include <cstdint>
#include <cstddef>

#define BATCH 8192
#define UNITS 1024
#define AR 12
#define RR 64
#define NP 30
#define ENC 76          // 12 + 64
#define G3 3072         // 3*UNITS
#define LDY 3200        // padded N for the fused GEMM (3072 gh + 12 ang + 64 rad + pad)

// output layout: a_oh | a_prob | r_oh | r_prob, each [B, NP, dim]
#define OFF_APROB (BATCH*NP*AR)
#define OFF_ROH   (2*BATCH*NP*AR)
#define OFF_RPROB (2*BATCH*NP*AR + BATCH*NP*RR)

// ------------------------- scratch (static device globals) -------------------------
__device__ float g_h[(size_t)BATCH * UNITS];
__device__ float g_Y[(size_t)BATCH * LDY];
__device__ float g_Wcat[(size_t)UNITS * LDY];
__device__ float g_C[(size_t)ENC * G3];
__device__ float g_cb[G3];
__device__ int   g_aidx[BATCH];
__device__ int   g_ridx[BATCH];

// ------------------------- threefry2x32 (exact JAX) -------------------------
__host__ __device__ __forceinline__ uint32_t rotl32(uint32_t x, int d) {
    return (x << d) | (x >> (32 - d));
}

__host__ __device__ __forceinline__ void threefry2x32(
    uint32_t k0, uint32_t k1, uint32_t c0, uint32_t c1,
    uint32_t& o0, uint32_t& o1)
{
    uint32_t ks2 = k0 ^ k1 ^ 0x1BD11BDAu;
    uint32_t x0 = c0 + k0;
    uint32_t x1 = c1 + k1;
    x0 += x1; x1 = rotl32(x1, 13); x1 ^= x0;
    x0 += x1; x1 = rotl32(x1, 15); x1 ^= x0;
    x0 += x1; x1 = rotl32(x1, 26); x1 ^= x0;
    x0 += x1; x1 = rotl32(x1, 6);  x1 ^= x0;
    x0 += k1; x1 += ks2 + 1u;
    x0 += x1; x1 = rotl32(x1, 17); x1 ^= x0;
    x0 += x1; x1 = rotl32(x1, 29); x1 ^= x0;
    x0 += x1; x1 = rotl32(x1, 16); x1 ^= x0;
    x0 += x1; x1 = rotl32(x1, 24); x1 ^= x0;
    x0 += ks2; x1 += k0 + 2u;
    x0 += x1; x1 = rotl32(x1, 13); x1 ^= x0;
    x0 += x1; x1 = rotl32(x1, 15); x1 ^= x0;
    x0 += x1; x1 = rotl32(x1, 26); x1 ^= x0;
    x0 += x1; x1 = rotl32(x1, 6);  x1 ^= x0;
    x0 += k0; x1 += k1 + 3u;
    x0 += x1; x1 = rotl32(x1, 17); x1 ^= x0;
    x0 += x1; x1 = rotl32(x1, 29); x1 ^= x0;
    x0 += x1; x1 = rotl32(x1, 16); x1 ^= x0;
    x0 += x1; x1 = rotl32(x1, 24); x1 ^= x0;
    x0 += k1; x1 += ks2 + 4u;
    x0 += x1; x1 = rotl32(x1, 13); x1 ^= x0;
    x0 += x1; x1 = rotl32(x1, 15); x1 ^= x0;
    x0 += x1; x1 = rotl32(x1, 26); x1 ^= x0;
    x0 += x1; x1 = rotl32(x1, 6);  x1 ^= x0;
    x0 += ks2; x1 += k0 + 5u;
    o0 = x0; o1 = x1;
}

// partitionable random_bits (JAX >= 0.5 default)
__device__ __forceinline__ float jax_gumbel_part(uint32_t k0, uint32_t k1, uint32_t i) {
    uint32_t o0, o1;
    threefry2x32(k0, k1, 0u, i, o0, o1);
    uint32_t bits = o0 ^ o1;
    float u = __uint_as_float((bits >> 9) | 0x3f800000u) - 1.0f;
    u = fmaxf(u, 1.17549435e-38f);
    return -logf(-logf(u));
}

// ------------------------- f32x2 packed-FMA helpers -------------------------
__device__ __forceinline__ uint64_t dup2(float v) {
    uint64_t r;
    asm("mov.b64 %0, {%1, %1};" : "=l"(r) : "f"(v));
    return r;
}
__device__ __forceinline__ void ffma2(uint64_t& d, uint64_t a, uint64_t b) {
    asm("fma.rn.f32x2 %0, %1, %2, %0;" : "+l"(d) : "l"(a), "l"(b));
}
__device__ __forceinline__ void unpack2(uint64_t v, float& lo, float& hi) {
    asm("mov.b64 {%0, %1}, %2;" : "=f"(lo), "=f"(hi) : "l"(v));
}
__device__ __forceinline__ void lds_v2b64(uint64_t& d0, uint64_t& d1, const float* p) {
    uint32_t a = (uint32_t)__cvta_generic_to_shared(p);
    asm("ld.shared.v2.b64 {%0, %1}, [%2];" : "=l"(d0), "=l"(d1) : "r"(a));
}

// ------------------------- setup kernels -------------------------
__global__ void build_Wcat(const float* __restrict__ U,
                           const float* __restrict__ Wang,
                           const float* __restrict__ Wrad)
{
    int idx = blockIdx.x * 256 + threadIdx.x;
    if (idx >= UNITS * LDY) return;
    int k = idx / LDY, n = idx % LDY;
    float v;
    if (n < G3)            v = U[(size_t)k * G3 + n];
    else if (n < G3 + AR)  v = Wang[k * AR + (n - G3)];
    else if (n < G3 + ENC) v = Wrad[k * RR + (n - G3 - AR)];
    else                   v = 0.0f;
    g_Wcat[idx] = v;
}

__global__ void build_C(const float* __restrict__ W_enc, const float* __restrict__ b_enc,
                        const float* __restrict__ W_gru, const float* __restrict__ b_gru)
{
    __shared__ float sw[16][80];
    int j = blockIdx.x * 128 + threadIdx.x;
    float acc[77];
    #pragma unroll
    for (int p = 0; p < 77; p++) acc[p] = 0.0f;
    for (int k0 = 0; k0 < UNITS; k0 += 16) {
        __syncthreads();
        for (int idx = threadIdx.x; idx < 16 * 77; idx += 128) {
            int kk = idx / 77, p = idx % 77;
            sw[kk][p] = (p < ENC) ? W_enc[p * UNITS + k0 + kk] : b_enc[k0 + kk];
        }
        __syncthreads();
        #pragma unroll 4
        for (int kk = 0; kk < 16; kk++) {
            float wg = W_gru[(size_t)(k0 + kk) * G3 + j];
            #pragma unroll
            for (int p = 0; p < 77; p++) acc[p] = fmaf(sw[kk][p], wg, acc[p]);
        }
    }
    for (int p = 0; p < ENC; p++) g_C[(size_t)p * G3 + j] = acc[p];
    g_cb[j] = acc[76] + b_gru[j];
}

__global__ void copy_h(const float* __restrict__ s)
{
    int idx = blockIdx.x * 256 + threadIdx.x;
    if (idx < BATCH * UNITS) g_h[idx] = s[idx];
}

// ------------------------- fused GEMM: Y = h @ Wcat (f32x2 packed) -------------------------
__global__ void __launch_bounds__(256, 2) sgemm_nt(int ntile0)
{
    __shared__ __align__(16) float As[2][8][128];
    __shared__ __align__(16) float Bs[2][8][128];
    const int K = UNITS;
    const int m0 = blockIdx.x * 128;
    const int n0 = (blockIdx.y + ntile0) * 128;
    const int tid = threadIdx.x;
    const int arow = tid >> 1, acol = (tid & 1) << 2;
    const int brow = tid >> 5, bcol = (tid & 31) << 2;
    const float* Ap = g_h    + (size_t)(m0 + arow) * K + acol;
    const float* Bp = g_Wcat + (size_t)brow * LDY + n0 + bcol;

    float4 av = *(const float4*)Ap;
    float4 bv = *(const float4*)Bp;
    As[0][acol + 0][arow] = av.x;
    As[0][acol + 1][arow] = av.y;
    As[0][acol + 2][arow] = av.z;
    As[0][acol + 3][arow] = av.w;
    *(float4*)&Bs[0][brow][bcol] = bv;
    __syncthreads();

    const int ty = tid >> 4, tx = tid & 15;
    // packed accumulators: accp[i][jp] covers output cols (2jp, 2jp+1)
    uint64_t accp[8][4];
    #pragma unroll
    for (int i = 0; i < 8; i++)
        #pragma unroll
        for (int jp = 0; jp < 4; jp++) accp[i][jp] = 0ull;

    int buf = 0;
    for (int k0 = 8; k0 < K + 8; k0 += 8) {
        float4 av2, bv2;
        const bool more = (k0 < K);
        if (more) {
            av2 = *(const float4*)(Ap + k0);
            bv2 = *(const float4*)(Bp + (size_t)k0 * LDY);
        }
        #pragma unroll
        for (int kk = 0; kk < 8; kk++) {
            float4 a0 = *(const float4*)&As[buf][kk][ty * 8];
            float4 a1 = *(const float4*)&As[buf][kk][ty * 8 + 4];
            uint64_t bp[4];
            lds_v2b64(bp[0], bp[1], &Bs[buf][kk][tx * 8]);
            lds_v2b64(bp[2], bp[3], &Bs[buf][kk][tx * 8 + 4]);
            uint64_t ad[8];
            ad[0] = dup2(a0.x); ad[1] = dup2(a0.y);
            ad[2] = dup2(a0.z); ad[3] = dup2(a0.w);
            ad[4] = dup2(a1.x); ad[5] = dup2(a1.y);
            ad[6] = dup2(a1.z); ad[7] = dup2(a1.w);
            #pragma unroll
            for (int i = 0; i < 8; i++)
                #pragma unroll
                for (int jp = 0; jp < 4; jp++)
                    ffma2(accp[i][jp], ad[i], bp[jp]);
        }
        if (more) {
            buf ^= 1;
            As[buf][acol + 0][arow] = av2.x;
            As[buf][acol + 1][arow] = av2.y;
            As[buf][acol + 2][arow] = av2.z;
            As[buf][acol + 3][arow] = av2.w;
            *(float4*)&Bs[buf][brow][bcol] = bv2;
            __syncthreads();
        }
    }
    #pragma unroll
    for (int i = 0; i < 8; i++) {
        float* Crow = g_Y + (size_t)(m0 + ty * 8 + i) * LDY + n0 + tx * 8;
        float4 v0, v1;
        unpack2(accp[i][0], v0.x, v0.y);
        unpack2(accp[i][1], v0.z, v0.w);
        unpack2(accp[i][2], v1.x, v1.y);
        unpack2(accp[i][3], v1.z, v1.w);
        *(float4*)Crow = v0;
        *(float4*)(Crow + 4) = v1;
    }
}

// ------------------------- GRU elementwise update -------------------------
__global__ void gru_update(const float* __restrict__ b_gru, int t)
{
    int idx = blockIdx.x * 256 + threadIdx.x;
    if (idx >= BATCH * UNITS) return;
    int b = idx >> 10, u = idx & 1023;
    float gxz, gxr, gxn;
    if (t == 0) {
        gxz = b_gru[u]; gxr = b_gru[1024 + u]; gxn = b_gru[2048 + u];
    } else {
        int a = g_aidx[b], r = 12 + g_ridx[b];
        const float* Ca = g_C + (size_t)a * G3;
        const float* Cr = g_C + (size_t)r * G3;
        gxz = Ca[u]        + Cr[u]        + g_cb[u];
        gxr = Ca[1024 + u] + Cr[1024 + u] + g_cb[1024 + u];
        gxn = Ca[2048 + u] + Cr[2048 + u] + g_cb[2048 + u];
    }
    const float* Yb = g_Y + (size_t)b * LDY;
    float z = 1.0f / (1.0f + expf(-(gxz + Yb[u])));
    float r = 1.0f / (1.0f + expf(-(gxr + Yb[1024 + u])));
    float n = tanhf(gxn + r * Yb[2048 + u]);
    float hv = g_h[idx];
    g_h[idx] = z * hv + (1.0f - z) * n;
}

// ------------------------- sampling + outputs -------------------------
__global__ void sample_kernel(const float* __restrict__ b_ang, const float* __restrict__ b_rad,
                              float* __restrict__ out, int t,
                              uint32_t ka0, uint32_t ka1, uint32_t kr0, uint32_t kr1)
{
    const int b = blockIdx.x;
    const int j = threadIdx.x;     // 64 threads
    __shared__ float s1[64], s2[64];
    __shared__ float sh_max, sh_sum;
    __shared__ int sh_arg;
    const float* __restrict__ Yb = g_Y + (size_t)b * LDY;

    // -------- radius (64 classes) --------
    float rl = Yb[G3 + AR + j] + b_rad[j];
    {
        float g = jax_gumbel_part(kr0, kr1, (uint32_t)b * RR + j);
        s1[j] = rl;
        s2[j] = rl + g;
    }
    __syncthreads();
    if (j == 0) {
        float m = s1[0], bg = s2[0];
        int bi = 0;
        for (int q = 1; q < RR; q++) {
            m = fmaxf(m, s1[q]);
            if (s2[q] > bg) { bg = s2[q]; bi = q; }
        }
        sh_max = m; sh_arg = bi; g_ridx[b] = bi;
    }
    __syncthreads();
    float re = expf(rl - sh_max);
    s1[j] = re;
    __syncthreads();
    if (j == 0) {
        float s = 0.0f;
        for (int q = 0; q < RR; q++) s += s1[q];
        sh_sum = s;
    }
    __syncthreads();
    {
        size_t ro = ((size_t)b * NP + t) * RR + j;
        out[OFF_ROH + ro]   = (j == sh_arg) ? 1.0f : 0.0f;
        out[OFF_RPROB + ro] = re / sh_sum;
    }
    __syncthreads();

    // -------- angle (12 classes) --------
    float al = 0.0f;
    if (j < AR) {
        al = Yb[G3 + j] + b_ang[j];
        float g = jax_gumbel_part(ka0, ka1, (uint32_t)b * AR + j);
        s1[j] = al;
        s2[j] = al + g;
    }
    __syncthreads();
    if (j == 0) {
        float m = s1[0], bg = s2[0];
        int bi = 0;
        for (int q = 1; q < AR; q++) {
            m = fmaxf(m, s1[q]);
            if (s2[q] > bg) { bg = s2[q]; bi = q; }
        }
        sh_max = m; sh_arg = bi; g_aidx[b] = bi;
    }
    __syncthreads();
    float ae = 0.0f;
    if (j < AR) { ae = expf(al - sh_max); s1[j] = ae; }
    __syncthreads();
    if (j == 0) {
        float s = 0.0f;
        for (int q = 0; q < AR; q++) s += s1[q];
        sh_sum = s;
    }
    __syncthreads();
    if (j < AR) {
        size_t ao = ((size_t)b * NP + t) * AR + j;
        out[ao]             = (j == sh_arg) ? 1.0f : 0.0f;
        out[OFF_APROB + ao] = ae / sh_sum;
    }
}

// ------------------------- launch -------------------------
extern "C" void kernel_launch(void* const* d_in, const int* in_sizes, int n_in,
                              void* d_out, int out_size)
{
    (void)in_sizes; (void)n_in; (void)out_size;
    const float* s     = (const float*)d_in[0];
    const float* W_enc = (const float*)d_in[1];
    const float* b_enc = (const float*)d_in[2];
    const float* W_gru = (const float*)d_in[3];
    const float* U_gru = (const float*)d_in[4];
    const float* b_gru = (const float*)d_in[5];
    const float* W_ang = (const float*)d_in[6];
    const float* b_ang = (const float*)d_in[7];
    const float* W_rad = (const float*)d_in[8];
    const float* b_rad = (const float*)d_in[9];
    float* out = (float*)d_out;

    // ---- host-side JAX key schedule (partitionable threefry, JAX >= 0.5) ----
    uint32_t ka0[NP], ka1[NP], kr0[NP], kr1[NP];
    for (int t = 0; t < NP; t++) {
        uint32_t kt0, kt1;
        threefry2x32(0u, 42u, 0u, (uint32_t)t, kt0, kt1);
        threefry2x32(kt0, kt1, 0u, 0u, ka0[t], ka1[t]);
        threefry2x32(kt0, kt1, 0u, 1u, kr0[t], kr1[t]);
    }

    build_Wcat<<<(UNITS * LDY + 255) / 256, 256>>>(U_gru, W_ang, W_rad);
    build_C<<<24, 128>>>(W_enc, b_enc, W_gru, b_gru);
    copy_h<<<(BATCH * UNITS + 255) / 256, 256>>>(s);

    // pre-loop GEMM: gh_1 = s @ U_gru (tiles 0..23, logits of s unused)
    sgemm_nt<<<dim3(64, 24), 256>>>(0);

    for (int t = 0; t < NP; t++) {
        gru_update<<<(BATCH * UNITS + 255) / 256, 256>>>(b_gru, t);
        if (t < NP - 1) sgemm_nt<<<dim3(64, 25), 256>>>(0);   // logits(h_t) + gh(t+1)
        else            sgemm_nt<<<dim3(64, 1), 256>>>(24);   // last step: logits only
        sample_kernel<<<BATCH, 64>>>(b_ang, b_rad, out, t,
                                     ka0[t], ka1[t], kr0[t], kr1[t]);
    }
}